// round 1
// baseline (speedup 1.0000x reference)
#include <cuda_runtime.h>
#include <cuda_bf16.h>
#include <math.h>

// Problem constants
#define BB 4
#define SS 2048
#define DD 1024
#define HH 16
#define DP 64            // depth per head
#define MM (BB*SS)       // 8192 rows for projections

static const long long OUT_ELEMS  = (long long)BB*SS*DD;            //   8,388,608
static const long long ATTN_ELEMS = (long long)BB*HH*SS*(long long)SS; // 268,435,456

// Scratch (allocation-free rule: __device__ globals)
__device__ float g_Qh[BB*HH*SS*DP];   // head-split Q  [b,h,s,d]
__device__ float g_Kh[BB*HH*SS*DP];
__device__ float g_Vh[BB*HH*SS*DP];
__device__ float g_ctx[BB*SS*DD];     // merged context [b,s,D]
__device__ float g_attn[BB*HH*(long long)SS*SS]; // fallback attn buffer

// ---------------------------------------------------------------------------
// SGEMM + bias: C = A[M,K] @ W[K,N] + bias[N]
// 64x64 tile, BK=16, 256 threads, 4x4 microtile, float4 smem reads.
// splitHeads: remap output to head-split layout [b,h,s,d].
// ---------------------------------------------------------------------------
__global__ void gemm_bias_kernel(const float* __restrict__ A,
                                 const float* __restrict__ W,
                                 const float* __restrict__ bias,
                                 float* __restrict__ C,
                                 int M, int N, int K, int splitHeads)
{
    __shared__ __align__(16) float AsT[16 * 68];   // [kk][row] padded
    __shared__ __align__(16) float Ws [16 * 64];   // [kk][col]

    const int t  = threadIdx.x;
    const int tx = t % 16;
    const int ty = t / 16;
    const int row0 = blockIdx.y * 64;
    const int col0 = blockIdx.x * 64;

    float acc[4][4];
#pragma unroll
    for (int i = 0; i < 4; i++)
#pragma unroll
        for (int j = 0; j < 4; j++) acc[i][j] = 0.0f;

    for (int k0 = 0; k0 < K; k0 += 16) {
        // load A tile (64 rows x 16 k) transposed into AsT[kk][row]
#pragma unroll
        for (int i = 0; i < 4; i++) {
            int r = t / 16 + i * 16;  // 0..63
            int c = t % 16;           // 0..15
            AsT[c * 68 + r] = A[(long long)(row0 + r) * K + k0 + c];
        }
        // load W tile (16 k x 64 cols)
#pragma unroll
        for (int i = 0; i < 4; i++) {
            int r = t / 64 + i * 4;   // 0..15
            int c = t % 64;
            Ws[r * 64 + c] = W[(long long)(k0 + r) * N + col0 + c];
        }
        __syncthreads();

#pragma unroll
        for (int kk = 0; kk < 16; kk++) {
            float4 a4 = *reinterpret_cast<const float4*>(&AsT[kk * 68 + ty * 4]);
            float4 b4 = *reinterpret_cast<const float4*>(&Ws [kk * 64 + tx * 4]);
            float a[4] = {a4.x, a4.y, a4.z, a4.w};
            float b[4] = {b4.x, b4.y, b4.z, b4.w};
#pragma unroll
            for (int i = 0; i < 4; i++)
#pragma unroll
                for (int j = 0; j < 4; j++) acc[i][j] = fmaf(a[i], b[j], acc[i][j]);
        }
        __syncthreads();
    }

#pragma unroll
    for (int i = 0; i < 4; i++) {
        int r = row0 + ty * 4 + i;
#pragma unroll
        for (int j = 0; j < 4; j++) {
            int c = col0 + tx * 4 + j;
            float v = acc[i][j] + bias[c];
            if (splitHeads) {
                int b = r / SS, s = r % SS;
                int h = c / DP, d = c % DP;
                C[(((long long)b * HH + h) * SS + s) * DP + d] = v;
            } else {
                C[(long long)r * N + c] = v;
            }
        }
    }
}

// ---------------------------------------------------------------------------
// Fused logits + softmax kernel.
// One CTA per (bh, 16 query rows). Full 2048-wide logit rows live in smem.
// ---------------------------------------------------------------------------
#define ATTN_SMEM_FLOATS (16*2048 + 16*64 + 64*65)
__global__ void attn_softmax_kernel(const float* __restrict__ mask,
                                    float* __restrict__ attn)
{
    extern __shared__ float sm[];
    float* logits = sm;                 // 16 * 2048
    float* Qs     = sm + 16 * 2048;     // 16 * 64
    float* Ks     = Qs + 16 * 64;       // 64 * 65 (padded)
    __shared__ float rinv[16];

    const int bh = blockIdx.y;
    const int q0 = blockIdx.x * 16;
    const int t  = threadIdx.x;         // 256 threads

    const float* Qb = g_Qh + (long long)bh * SS * DP;
    const float* Kb = g_Kh + (long long)bh * SS * DP;

    // load 16x64 Q tile
#pragma unroll
    for (int i = 0; i < 4; i++) {
        int idx = t + i * 256;
        int r = idx / 64, c = idx % 64;
        Qs[r * 64 + c] = Qb[(long long)(q0 + r) * DP + c];
    }

    const int qg   = t / 32;  // 0..7 -> rows qg*2, qg*2+1
    const int lane = t % 32;  // cols lane, lane+32 within key tile
    const float scale = 0.125f;  // 1/sqrt(64)

    for (int k0 = 0; k0 < SS; k0 += 64) {
        __syncthreads();   // protect Ks reuse + Qs on first iter
        // load K tile 64x64 (padded rows of 65)
#pragma unroll
        for (int i = 0; i < 16; i++) {
            int idx = t + i * 256;
            int r = idx / 64, c = idx % 64;
            Ks[r * 65 + c] = Kb[(long long)(k0 + r) * DP + c];
        }
        __syncthreads();

        float a00 = 0.f, a01 = 0.f, a10 = 0.f, a11 = 0.f;
        const float* q0p = &Qs[(qg * 2 + 0) * 64];
        const float* q1p = &Qs[(qg * 2 + 1) * 64];
        const float* k0p = &Ks[lane * 65];
        const float* k1p = &Ks[(lane + 32) * 65];
#pragma unroll
        for (int kk = 0; kk < 64; kk++) {
            float qv0 = q0p[kk];
            float qv1 = q1p[kk];
            float kv0 = k0p[kk];
            float kv1 = k1p[kk];
            a00 = fmaf(qv0, kv0, a00);
            a01 = fmaf(qv0, kv1, a01);
            a10 = fmaf(qv1, kv0, a10);
            a11 = fmaf(qv1, kv1, a11);
        }
        const float* m0 = mask + (long long)(q0 + qg * 2 + 0) * SS + k0;
        const float* m1 = mask + (long long)(q0 + qg * 2 + 1) * SS + k0;
        logits[(qg * 2 + 0) * 2048 + k0 + lane]      = fmaf(m0[lane],      -1e9f, a00 * scale);
        logits[(qg * 2 + 0) * 2048 + k0 + lane + 32] = fmaf(m0[lane + 32], -1e9f, a01 * scale);
        logits[(qg * 2 + 1) * 2048 + k0 + lane]      = fmaf(m1[lane],      -1e9f, a10 * scale);
        logits[(qg * 2 + 1) * 2048 + k0 + lane + 32] = fmaf(m1[lane + 32], -1e9f, a11 * scale);
    }
    __syncthreads();

    // softmax: 16 threads per row
    {
        const int r = t / 16;
        const int l = t % 16;
        float* row = logits + r * 2048;
        float mx = -INFINITY;
        for (int i = l; i < 2048; i += 16) mx = fmaxf(mx, row[i]);
#pragma unroll
        for (int o = 8; o > 0; o >>= 1)
            mx = fmaxf(mx, __shfl_xor_sync(0xffffffffu, mx, o, 16));
        float ssum = 0.f;
        for (int i = l; i < 2048; i += 16) {
            float e = __expf(row[i] - mx);
            row[i] = e;
            ssum += e;
        }
#pragma unroll
        for (int o = 8; o > 0; o >>= 1)
            ssum += __shfl_xor_sync(0xffffffffu, ssum, o, 16);
        if (l == 0) rinv[r] = 1.0f / ssum;
    }
    __syncthreads();

    // normalize + write out (16 rows are contiguous in attn)
    float* outp = attn + ((long long)bh * SS + q0) * SS;
#pragma unroll
    for (int i = 0; i < 128; i++) {
        int idx = t + i * 256;
        outp[idx] = logits[idx] * rinv[idx >> 11];
    }
}

// ---------------------------------------------------------------------------
// ctx = attn @ V per (b,h). M=2048, N=64, K=2048. 64x64 tile, BK=16.
// Output merged into [b, s, D] layout.
// ---------------------------------------------------------------------------
__global__ void ctx_kernel(const float* __restrict__ attn)
{
    __shared__ __align__(16) float AsT[16 * 68];
    __shared__ __align__(16) float Vs [16 * 64];

    const int t  = threadIdx.x;
    const int tx = t % 16;
    const int ty = t / 16;
    const int bh = blockIdx.y;
    const int b  = bh / HH;
    const int h  = bh % HH;
    const int row0 = blockIdx.x * 64;

    const float* A = attn + (long long)bh * SS * SS;
    const float* V = g_Vh + (long long)bh * SS * DP;

    float acc[4][4];
#pragma unroll
    for (int i = 0; i < 4; i++)
#pragma unroll
        for (int j = 0; j < 4; j++) acc[i][j] = 0.0f;

    for (int k0 = 0; k0 < SS; k0 += 16) {
#pragma unroll
        for (int i = 0; i < 4; i++) {
            int r = t / 16 + i * 16;
            int c = t % 16;
            AsT[c * 68 + r] = A[(long long)(row0 + r) * SS + k0 + c];
        }
#pragma unroll
        for (int i = 0; i < 4; i++) {
            int r = t / 64 + i * 4;
            int c = t % 64;
            Vs[r * 64 + c] = V[(long long)(k0 + r) * DP + c];
        }
        __syncthreads();

#pragma unroll
        for (int kk = 0; kk < 16; kk++) {
            float4 a4 = *reinterpret_cast<const float4*>(&AsT[kk * 68 + ty * 4]);
            float4 b4 = *reinterpret_cast<const float4*>(&Vs [kk * 64 + tx * 4]);
            float a[4] = {a4.x, a4.y, a4.z, a4.w};
            float bb[4] = {b4.x, b4.y, b4.z, b4.w};
#pragma unroll
            for (int i = 0; i < 4; i++)
#pragma unroll
                for (int j = 0; j < 4; j++) acc[i][j] = fmaf(a[i], bb[j], acc[i][j]);
        }
        __syncthreads();
    }

#pragma unroll
    for (int i = 0; i < 4; i++) {
        int s = row0 + ty * 4 + i;
#pragma unroll
        for (int j = 0; j < 4; j++) {
            int d = tx * 4 + j;
            g_ctx[((long long)b * SS + s) * DD + h * DP + d] = acc[i][j];
        }
    }
}

// ---------------------------------------------------------------------------
extern "C" void kernel_launch(void* const* d_in, const int* in_sizes, int n_in,
                              void* d_out, int out_size)
{
    const float* q    = (const float*)d_in[0];
    const float* k    = (const float*)d_in[1];
    const float* v    = (const float*)d_in[2];
    const float* mask = (const float*)d_in[3];
    const float* Wq   = (const float*)d_in[4];
    const float* bq   = (const float*)d_in[5];
    const float* Wk   = (const float*)d_in[6];
    const float* bk   = (const float*)d_in[7];
    const float* Wv   = (const float*)d_in[8];
    const float* bv   = (const float*)d_in[9];
    const float* Wo   = (const float*)d_in[10];
    const float* bo   = (const float*)d_in[11];

    float* outp = (float*)d_out;
    float* attnp = nullptr;
    if ((long long)out_size >= OUT_ELEMS + ATTN_ELEMS) {
        attnp = outp + OUT_ELEMS;          // tuple order: (out, attn)
    } else {
        void* sym = nullptr;
        cudaGetSymbolAddress(&sym, g_attn);
        attnp = (float*)sym;
    }

    float* Qh = nullptr; cudaGetSymbolAddress((void**)&Qh, g_Qh);
    float* Kh = nullptr; cudaGetSymbolAddress((void**)&Kh, g_Kh);
    float* Vh = nullptr; cudaGetSymbolAddress((void**)&Vh, g_Vh);
    float* ctx = nullptr; cudaGetSymbolAddress((void**)&ctx, g_ctx);

    dim3 gThreads(256);
    dim3 gGridProj(DD / 64, MM / 64);   // (16, 128)

    // Q/K/V projections into head-split scratch
    gemm_bias_kernel<<<gGridProj, gThreads>>>(q, Wq, bq, Qh, MM, DD, DD, 1);
    gemm_bias_kernel<<<gGridProj, gThreads>>>(k, Wk, bk, Kh, MM, DD, DD, 1);
    gemm_bias_kernel<<<gGridProj, gThreads>>>(v, Wv, bv, Vh, MM, DD, DD, 1);

    // logits + softmax -> attn
    size_t smemBytes = ATTN_SMEM_FLOATS * sizeof(float);
    cudaFuncSetAttribute(attn_softmax_kernel,
                         cudaFuncAttributeMaxDynamicSharedMemorySize,
                         (int)smemBytes);
    dim3 aGrid(SS / 16, BB * HH);       // (128, 64)
    attn_softmax_kernel<<<aGrid, gThreads, smemBytes>>>(mask, attnp);

    // ctx = attn @ V (merged layout)
    dim3 cGrid(SS / 64, BB * HH);       // (32, 64)
    ctx_kernel<<<cGrid, gThreads>>>(attnp);

    // output projection
    gemm_bias_kernel<<<gGridProj, gThreads>>>(ctx, Wo, bo, outp, MM, DD, DD, 0);
}

// round 3
// speedup vs baseline: 2.5730x; 2.5730x over previous
#include <cuda_runtime.h>
#include <cuda_bf16.h>
#include <math.h>

#define BB 4
#define SS 2048
#define DD 1024
#define HH 16
#define DP 64
#define MM (BB*SS)

static const long long OUT_ELEMS  = (long long)BB*SS*DD;
static const long long ATTN_ELEMS = (long long)BB*HH*(long long)SS*SS;

// Scratch (__device__ globals per allocation rules)
__device__ float g_Qh[BB*HH*SS*DP];
__device__ float g_Kh[BB*HH*SS*DP];
__device__ float g_Vh[BB*HH*SS*DP];
__device__ float g_ctx[BB*SS*DD];
__device__ float g_attn[BB*HH*(long long)SS*SS];

// ---------------------------------------------------------------------------
__device__ __forceinline__ unsigned f2tf(float x) {
    unsigned r;
    asm("cvt.rna.tf32.f32 %0, %1;" : "=r"(r) : "f"(x));
    return r;
}

__device__ __forceinline__ void mma_tf32(float c[4], const unsigned a[4], const unsigned b[2]) {
    asm volatile(
        "mma.sync.aligned.m16n8k8.row.col.f32.tf32.tf32.f32 "
        "{%0,%1,%2,%3}, {%4,%5,%6,%7}, {%8,%9}, {%0,%1,%2,%3};"
        : "+f"(c[0]), "+f"(c[1]), "+f"(c[2]), "+f"(c[3])
        : "r"(a[0]), "r"(a[1]), "r"(a[2]), "r"(a[3]), "r"(b[0]), "r"(b[1]));
}

// ---------------------------------------------------------------------------
// Generic TF32 tensor-core GEMM:  C = alpha * A @ op(B) + bias
//  BT=false: B is [K,N] row-major.  BT=true: B is [N,K] row-major (B^T used).
//  SPLIT: 0 = C[z*sC + r*N+c]; 1 = head-split store [b,h,s,d];
//         2 = merge store ctx layout [b,s,D] from per-(b,h) rows.
// ---------------------------------------------------------------------------
template<int BM, int BN, int BK, int WM, int WN, bool BT, int SPLIT>
__global__ __launch_bounds__(256)
void mma_gemm_kernel(const float* __restrict__ A,
                     const float* __restrict__ Bm,
                     const float* __restrict__ bias,
                     float* __restrict__ C,
                     int M, int N, int K,
                     long long sA, long long sB, long long sC,
                     float alpha)
{
    constexpr int AP = BK + 4;
    constexpr int BP = BN + 4;
    __shared__ unsigned As[BM * AP];
    __shared__ unsigned Bs[BK * BP];

    const int tid  = threadIdx.x;
    const int lane = tid & 31;
    const int warp = tid >> 5;
    constexpr int WN_CNT = BN / WN;
    const int wm = warp / WN_CNT;
    const int wn = warp % WN_CNT;
    const int row0 = blockIdx.y * BM;
    const int col0 = blockIdx.x * BN;
    const int z    = blockIdx.z;

    A  += (long long)z * sA;
    Bm += (long long)z * sB;

    constexpr int MT = WM / 16;
    constexpr int NT = WN / 8;
    float cfr[MT][NT][4];
#pragma unroll
    for (int mt = 0; mt < MT; mt++)
#pragma unroll
        for (int nt = 0; nt < NT; nt++)
#pragma unroll
            for (int i = 0; i < 4; i++) cfr[mt][nt][i] = 0.0f;

    for (int k0 = 0; k0 < K; k0 += BK) {
        // ---- load A tile [BM x BK] as tf32, layout As[m][k]
#pragma unroll
        for (int i = 0; i < (BM * BK / 4) / 256; i++) {
            int idx = tid + i * 256;
            int r   = idx / (BK / 4);
            int kq  = (idx % (BK / 4)) * 4;
            float4 v = *(const float4*)(A + (long long)(row0 + r) * K + k0 + kq);
            As[r * AP + kq + 0] = f2tf(v.x);
            As[r * AP + kq + 1] = f2tf(v.y);
            As[r * AP + kq + 2] = f2tf(v.z);
            As[r * AP + kq + 3] = f2tf(v.w);
        }
        // ---- load B tile [BK x BN], layout Bs[k][n]
        if (BT) {
#pragma unroll
            for (int i = 0; i < (BN * BK / 4) / 256; i++) {
                int idx = tid + i * 256;
                int n   = idx / (BK / 4);
                int kq  = (idx % (BK / 4)) * 4;
                float4 v = *(const float4*)(Bm + (long long)(col0 + n) * K + k0 + kq);
                Bs[(kq + 0) * BP + n] = f2tf(v.x);
                Bs[(kq + 1) * BP + n] = f2tf(v.y);
                Bs[(kq + 2) * BP + n] = f2tf(v.z);
                Bs[(kq + 3) * BP + n] = f2tf(v.w);
            }
        } else {
#pragma unroll
            for (int i = 0; i < (BK * BN / 4) / 256; i++) {
                int idx = tid + i * 256;
                int kk  = idx / (BN / 4);
                int nq  = (idx % (BN / 4)) * 4;
                float4 v = *(const float4*)(Bm + (long long)(k0 + kk) * N + col0 + nq);
                Bs[kk * BP + nq + 0] = f2tf(v.x);
                Bs[kk * BP + nq + 1] = f2tf(v.y);
                Bs[kk * BP + nq + 2] = f2tf(v.z);
                Bs[kk * BP + nq + 3] = f2tf(v.w);
            }
        }
        __syncthreads();

#pragma unroll
        for (int ks = 0; ks < BK / 8; ks++) {
            unsigned af[MT][4];
            unsigned bf[NT][2];
            const int kb = ks * 8 + (lane & 3);
#pragma unroll
            for (int mt = 0; mt < MT; mt++) {
                int r = wm * WM + mt * 16 + (lane >> 2);
                af[mt][0] = As[r * AP + kb];
                af[mt][1] = As[(r + 8) * AP + kb];
                af[mt][2] = As[r * AP + kb + 4];
                af[mt][3] = As[(r + 8) * AP + kb + 4];
            }
#pragma unroll
            for (int nt = 0; nt < NT; nt++) {
                int cc = wn * WN + nt * 8 + (lane >> 2);
                bf[nt][0] = Bs[kb * BP + cc];
                bf[nt][1] = Bs[(kb + 4) * BP + cc];
            }
#pragma unroll
            for (int mt = 0; mt < MT; mt++)
#pragma unroll
                for (int nt = 0; nt < NT; nt++)
                    mma_tf32(cfr[mt][nt], af[mt], bf[nt]);
        }
        __syncthreads();
    }

    // ---- epilogue
#pragma unroll
    for (int mt = 0; mt < MT; mt++) {
#pragma unroll
        for (int nt = 0; nt < NT; nt++) {
#pragma unroll
            for (int i = 0; i < 4; i++) {
                int r = row0 + wm * WM + mt * 16 + (lane >> 2) + ((i >= 2) ? 8 : 0);
                int c = col0 + wn * WN + nt * 8 + (lane & 3) * 2 + (i & 1);
                float v = cfr[mt][nt][i] * alpha + (bias ? bias[c] : 0.0f);
                if (SPLIT == 0) {
                    C[(long long)z * sC + (long long)r * N + c] = v;
                } else if (SPLIT == 1) {
                    int b = r / SS, s = r % SS;
                    int h = c / DP, d = c % DP;
                    C[(((long long)b * HH + h) * SS + s) * DP + d] = v;
                } else { // SPLIT == 2 : merge ctx
                    int b = z / HH, h = z % HH;
                    C[((long long)b * SS + r) * DD + h * DP + c] = v;
                }
            }
        }
    }
}

// ---------------------------------------------------------------------------
// In-place row softmax over attn buffer: one 128-thread block per row.
// Row = 2048 floats, held in registers (16 per thread).
// ---------------------------------------------------------------------------
__global__ __launch_bounds__(128)
void softmax_kernel(float* __restrict__ attn, const float* __restrict__ mask)
{
    const long long row = blockIdx.x;
    const int q = (int)(row % SS);
    float* p = attn + row * SS;
    const float* m = mask + (long long)q * SS;
    const int t = threadIdx.x;

    float4 vals[4];
    float mx = -INFINITY;
#pragma unroll
    for (int i = 0; i < 4; i++) {
        float4 lv = ((const float4*)p)[t + i * 128];
        float4 mv = ((const float4*)m)[t + i * 128];
        lv.x = fmaf(mv.x, -1e9f, lv.x);
        lv.y = fmaf(mv.y, -1e9f, lv.y);
        lv.z = fmaf(mv.z, -1e9f, lv.z);
        lv.w = fmaf(mv.w, -1e9f, lv.w);
        vals[i] = lv;
        mx = fmaxf(mx, fmaxf(fmaxf(lv.x, lv.y), fmaxf(lv.z, lv.w)));
    }

    __shared__ float red[4];
#pragma unroll
    for (int o = 16; o > 0; o >>= 1)
        mx = fmaxf(mx, __shfl_xor_sync(0xffffffffu, mx, o));
    if ((t & 31) == 0) red[t >> 5] = mx;
    __syncthreads();
    mx = fmaxf(fmaxf(red[0], red[1]), fmaxf(red[2], red[3]));
    __syncthreads();

    float ssum = 0.0f;
#pragma unroll
    for (int i = 0; i < 4; i++) {
        vals[i].x = __expf(vals[i].x - mx);
        vals[i].y = __expf(vals[i].y - mx);
        vals[i].z = __expf(vals[i].z - mx);
        vals[i].w = __expf(vals[i].w - mx);
        ssum += vals[i].x + vals[i].y + vals[i].z + vals[i].w;
    }
#pragma unroll
    for (int o = 16; o > 0; o >>= 1)
        ssum += __shfl_xor_sync(0xffffffffu, ssum, o);
    if ((t & 31) == 0) red[t >> 5] = ssum;
    __syncthreads();
    ssum = red[0] + red[1] + red[2] + red[3];
    const float rinv = 1.0f / ssum;

#pragma unroll
    for (int i = 0; i < 4; i++) {
        float4 v = vals[i];
        v.x *= rinv; v.y *= rinv; v.z *= rinv; v.w *= rinv;
        ((float4*)p)[t + i * 128] = v;
    }
}

// ---------------------------------------------------------------------------
extern "C" void kernel_launch(void* const* d_in, const int* in_sizes, int n_in,
                              void* d_out, int out_size)
{
    const float* q    = (const float*)d_in[0];
    const float* k    = (const float*)d_in[1];
    const float* v    = (const float*)d_in[2];
    const float* mask = (const float*)d_in[3];
    const float* Wq   = (const float*)d_in[4];
    const float* bq   = (const float*)d_in[5];
    const float* Wk   = (const float*)d_in[6];
    const float* bk   = (const float*)d_in[7];
    const float* Wv   = (const float*)d_in[8];
    const float* bv   = (const float*)d_in[9];
    const float* Wo   = (const float*)d_in[10];
    const float* bo   = (const float*)d_in[11];

    float* outp  = (float*)d_out;
    float* attnp = nullptr;
    if ((long long)out_size >= OUT_ELEMS + ATTN_ELEMS) {
        attnp = outp + OUT_ELEMS;
    } else {
        void* sym = nullptr;
        cudaGetSymbolAddress(&sym, g_attn);
        attnp = (float*)sym;
    }

    float* Qh = nullptr;  cudaGetSymbolAddress((void**)&Qh,  g_Qh);
    float* Kh = nullptr;  cudaGetSymbolAddress((void**)&Kh,  g_Kh);
    float* Vh = nullptr;  cudaGetSymbolAddress((void**)&Vh,  g_Vh);
    float* ctx = nullptr; cudaGetSymbolAddress((void**)&ctx, g_ctx);

    // --- Q/K/V projections (head-split outputs) ---
    mma_gemm_kernel<128,128,16,64,32,false,1><<<dim3(8,64,1), 256>>>(
        q, Wq, bq, Qh, MM, DD, DD, 0, 0, 0, 1.0f);
    mma_gemm_kernel<128,128,16,64,32,false,1><<<dim3(8,64,1), 256>>>(
        k, Wk, bk, Kh, MM, DD, DD, 0, 0, 0, 1.0f);
    mma_gemm_kernel<128,128,16,64,32,false,1><<<dim3(8,64,1), 256>>>(
        v, Wv, bv, Vh, MM, DD, DD, 0, 0, 0, 1.0f);

    // --- logits = (Q @ K^T) / 8, batched over 64 (b,h) ---
    mma_gemm_kernel<128,128,16,64,32,true,0><<<dim3(16,16,BB*HH), 256>>>(
        Qh, Kh, nullptr, attnp, SS, SS, DP,
        (long long)SS*DP, (long long)SS*DP, (long long)SS*SS, 0.125f);

    // --- softmax in place (with mask) ---
    softmax_kernel<<<BB*HH*SS, 128>>>(attnp, mask);

    // --- ctx = attn @ V, merged layout ---
    mma_gemm_kernel<128,64,16,32,32,false,2><<<dim3(1,16,BB*HH), 256>>>(
        attnp, Vh, nullptr, ctx, SS, DP, SS,
        (long long)SS*SS, (long long)SS*DP, 0, 1.0f);

    // --- output projection ---
    mma_gemm_kernel<128,128,16,64,32,false,0><<<dim3(8,64,1), 256>>>(
        ctx, Wo, bo, outp, MM, DD, DD, 0, 0, 0, 1.0f);
}